// round 9
// baseline (speedup 1.0000x reference)
#include <cuda_runtime.h>
#include <cuda_bf16.h>
#include <math.h>

#define BB   64
#define EE   512
#define NN   2048
#define IMGS 64
#define EPSF 1e-8f

// ---- scratch (static device globals; no allocation) ----
__device__ __nv_bfloat16 g_y[BB * IMGS * NN];   // 16 MiB  [b][o][n]
__device__ float g_colpart[BB * 16 * NN];       // 8 MiB   [b][chunk][n]
__device__ float g_rowmean[BB * EE];            // 128 KiB
__device__ unsigned g_mm[6];                    // min/max per channel (encoded)

// order-preserving float<->uint encoding for atomic min/max
__device__ __forceinline__ unsigned fenc(float f) {
    unsigned u = __float_as_uint(f);
    return (u & 0x80000000u) ? ~u : (u | 0x80000000u);
}
__device__ __forceinline__ float fdec(unsigned e) {
    unsigned u = (e & 0x80000000u) ? (e ^ 0x80000000u) : ~e;
    return __uint_as_float(u);
}

__device__ __forceinline__ unsigned smem_u32(const void* p) {
    unsigned a;
    asm("{ .reg .u64 t; cvta.to.shared.u64 t, %1; cvt.u32.u64 %0, t; }"
        : "=r"(a) : "l"(p));
    return a;
}

// block-wide minmax -> global atomics (entry sync so it can be called twice)
__device__ __forceinline__ void block_minmax_atomic(float mn, float mx, int ch) {
    __shared__ float smn[8], smx[8];
    __syncthreads();
    #pragma unroll
    for (int o = 16; o; o >>= 1) {
        mn = fminf(mn, __shfl_down_sync(0xFFFFFFFFu, mn, o));
        mx = fmaxf(mx, __shfl_down_sync(0xFFFFFFFFu, mx, o));
    }
    int lane = threadIdx.x & 31, warp = threadIdx.x >> 5;
    if (lane == 0) { smn[warp] = mn; smx[warp] = mx; }
    __syncthreads();
    if (threadIdx.x == 0) {
        float a = smn[0], c = smx[0];
        #pragma unroll
        for (int w = 1; w < 8; ++w) { a = fminf(a, smn[w]); c = fmaxf(c, smx[w]); }
        atomicMin(&g_mm[2 * ch], fenc(a));
        atomicMax(&g_mm[2 * ch + 1], fenc(c));
    }
}

// ---------------------------------------------------------------------------
// Pass 1: one CTA per (batch, 32-row chunk). Streams input once.
//  - per-row mean -> g_rowmean (temporal raw)
//  - rows 32c+{8q+3, 8q+4} (q=0..3) -> y rows 4c+q  (re-read from L2 after
//    stats; no smem stash -> high occupancy)
//  - partial column sums over the 32 rows -> g_colpart
// ---------------------------------------------------------------------------
__global__ void __launch_bounds__(256) k_pass1(const float* __restrict__ x) {
    const int chunk = blockIdx.x;   // 0..15
    const int b     = blockIdx.y;   // 0..63
    const int t     = threadIdx.x;  // 0..255
    const int lane  = t & 31, warp = t >> 5;

    if (chunk == 0 && b == 0) {     // fold g_mm init in (consumers run later)
        if (t < 3) g_mm[2 * t] = 0xFFFFFFFFu;
        else if (t < 6) g_mm[2 * (t - 3) + 1] = 0u;
    }

    __shared__ float wsum[8][32];   // [warp][row]
    __shared__ float wsq[8][8];     // [warp][selected-row]
    __shared__ float rsum[32], rsq[8];

    float4 cs0 = make_float4(0.f, 0.f, 0.f, 0.f);
    float4 cs1 = make_float4(0.f, 0.f, 0.f, 0.f);

    const float4* base = (const float4*)x + (size_t)(b * EE + chunk * 32) * (NN / 4);

    #pragma unroll
    for (int r = 0; r < 32; ++r) {
        const float4* rp = base + (size_t)r * (NN / 4);
        float4 v0 = rp[t];
        float4 v1 = rp[t + 256];

        cs0.x += v0.x; cs0.y += v0.y; cs0.z += v0.z; cs0.w += v0.w;
        cs1.x += v1.x; cs1.y += v1.y; cs1.z += v1.z; cs1.w += v1.w;

        float s = (v0.x + v0.y) + (v0.z + v0.w) + (v1.x + v1.y) + (v1.z + v1.w);
        #pragma unroll
        for (int o = 16; o; o >>= 1)
            s += __shfl_down_sync(0xFFFFFFFFu, s, o);
        if (lane == 0) wsum[warp][r] = s;

        if ((r & 7) == 3 || (r & 7) == 4) {   // selected rows: sumsq too
            const int si = (r >> 3) * 2 + ((r & 7) == 4);
            float q = v0.x * v0.x + v0.y * v0.y + v0.z * v0.z + v0.w * v0.w +
                      v1.x * v1.x + v1.y * v1.y + v1.z * v1.z + v1.w * v1.w;
            #pragma unroll
            for (int o = 16; o; o >>= 1)
                q += __shfl_down_sync(0xFFFFFFFFu, q, o);
            if (lane == 0) wsq[warp][si] = q;
        }
    }
    __syncthreads();
    if (t < 32) {
        float S = 0.f;
        #pragma unroll
        for (int w = 0; w < 8; ++w) S += wsum[w][t];
        rsum[t] = S;
        g_rowmean[b * EE + chunk * 32 + t] = S * (1.0f / NN);
    } else if (t < 40) {
        const int p = t - 32;
        float Q = 0.f;
        #pragma unroll
        for (int w = 0; w < 8; ++w) Q += wsq[w][p];
        rsq[p] = Q;
    }
    __syncthreads();

    // y rows: re-read selected row pairs (L2-hot), center+normalize, bf16
    #pragma unroll
    for (int yr = 0; yr < 4; ++yr) {
        const int r3 = yr * 8 + 3, r4 = yr * 8 + 4;
        const float mA = rsum[r3] * (1.0f / NN);
        const float mB = rsum[r4] * (1.0f / NN);
        const float iA = 0.5f / (sqrtf(fmaxf(rsq[2 * yr]     - (float)NN * mA * mA, 0.f)) + EPSF);
        const float iB = 0.5f / (sqrtf(fmaxf(rsq[2 * yr + 1] - (float)NN * mB * mB, 0.f)) + EPSF);
        const float4* rpA = base + (size_t)r3 * (NN / 4);
        const float4* rpB = base + (size_t)r4 * (NN / 4);
        uint2* yb = (uint2*)(g_y + (size_t)(b * IMGS + chunk * 4 + yr) * NN);
        #pragma unroll
        for (int u = 0; u < 2; ++u) {
            float4 a = rpA[t + 256 * u];
            float4 c = rpB[t + 256 * u];
            float4 y;
            y.x = (a.x - mA) * iA + (c.x - mB) * iB;
            y.y = (a.y - mA) * iA + (c.y - mB) * iB;
            y.z = (a.z - mA) * iA + (c.z - mB) * iB;
            y.w = (a.w - mA) * iA + (c.w - mB) * iB;
            __nv_bfloat162 h0 = __floats2bfloat162_rn(y.x, y.y);
            __nv_bfloat162 h1 = __floats2bfloat162_rn(y.z, y.w);
            uint2 pk;
            pk.x = *(unsigned*)&h0;
            pk.y = *(unsigned*)&h1;
            yb[t + 256 * u] = pk;
        }
    }

    float4* cp = (float4*)g_colpart + (size_t)(b * 16 + chunk) * (NN / 4);
    cp[t] = cs0; cp[t + 256] = cs1;
}

// ---------------------------------------------------------------------------
// Fused middle kernel, grid = 128:
//  blocks 0..63  : corr GEMM (1 CTA per batch), bf16 mma.sync, reg-prefetch
//  blocks 64..127: temporal+spatial bilinear views (1 CTA per batch)
// ---------------------------------------------------------------------------
__global__ void __launch_bounds__(256) k_fused(float* __restrict__ out) {
    __shared__ __align__(16) char smraw[16384];  // union: gemm dbuf / view arrays
    const int t = threadIdx.x;

    if (blockIdx.x < 64) {
        // ================= GEMM branch =================
        const int b    = blockIdx.x;
        const int warp = t >> 5, lane = t & 31;
        const int wm   = warp >> 1;        // 0..3 -> rows 16*wm
        const int wn   = warp & 1;         // 0..1 -> cols 32*wn

        char (*sm)[64 * 128] = (char (*)[64 * 128])smraw;  // [2][8192] dbuf
        const __nv_bfloat16* Yb = g_y + (size_t)b * IMGS * NN;

        const int lrow = t >> 2;           // loader row 0..63
        const int lch0 = (t & 3) * 2;      // two 16B chunks of a 128B row

        const int arow  = wm * 16 + (lane & 15);
        const int brow0 = wn * 32 + (lane & 15);
        const int brow1 = wn * 32 + 16 + (lane & 15);
        const int chalf = (lane >> 4) * 16;
        const unsigned smb = smem_u32(smraw);

        float acc[4][4];
        #pragma unroll
        for (int j = 0; j < 4; ++j)
            #pragma unroll
            for (int r = 0; r < 4; ++r) acc[j][r] = 0.f;

        uint4 pv0, pv1;
        {   // preload tile 0
            const uint4* src = (const uint4*)(Yb + (size_t)lrow * NN);
            pv0 = src[lch0]; pv1 = src[lch0 + 1];
            int off0 = lrow * 128 + lch0 * 16;
            *(uint4*)(smraw + (off0 ^ ((lrow & 7) << 4))) = pv0;
            *(uint4*)(smraw + ((off0 + 16) ^ ((lrow & 7) << 4))) = pv1;
        }
        __syncthreads();

        for (int kt = 0; kt < 32; ++kt) {
            const int buf = kt & 1;
            if (kt + 1 < 32) {  // issue next-tile loads early (regs)
                const uint4* src = (const uint4*)(Yb + (size_t)lrow * NN + (kt + 1) * 64);
                pv0 = src[lch0]; pv1 = src[lch0 + 1];
            }

            const unsigned base = smb + buf * (64 * 128);
            #pragma unroll
            for (int ks = 0; ks < 4; ++ks) {
                const int kb = ks * 32;
                unsigned a0, a1, a2, a3;
                {
                    int off = arow * 128 + kb + chalf;
                    unsigned ad = base + (off ^ ((arow & 7) << 4));
                    asm volatile("ldmatrix.sync.aligned.m8n8.x4.shared.b16 "
                                 "{%0,%1,%2,%3}, [%4];"
                                 : "=r"(a0), "=r"(a1), "=r"(a2), "=r"(a3) : "r"(ad));
                }
                unsigned q0, q1, q2, q3, p0, p1, p2, p3;
                {
                    int off = brow0 * 128 + kb + chalf;
                    unsigned ad = base + (off ^ ((brow0 & 7) << 4));
                    asm volatile("ldmatrix.sync.aligned.m8n8.x4.shared.b16 "
                                 "{%0,%1,%2,%3}, [%4];"
                                 : "=r"(q0), "=r"(q1), "=r"(q2), "=r"(q3) : "r"(ad));
                }
                {
                    int off = brow1 * 128 + kb + chalf;
                    unsigned ad = base + (off ^ ((brow1 & 7) << 4));
                    asm volatile("ldmatrix.sync.aligned.m8n8.x4.shared.b16 "
                                 "{%0,%1,%2,%3}, [%4];"
                                 : "=r"(p0), "=r"(p1), "=r"(p2), "=r"(p3) : "r"(ad));
                }
                #define MMA(J, B0, B1)                                              \
                    asm volatile("mma.sync.aligned.m16n8k16.row.col.f32.bf16.bf16.f32 " \
                                 "{%0,%1,%2,%3}, {%4,%5,%6,%7}, {%8,%9}, {%0,%1,%2,%3};" \
                                 : "+f"(acc[J][0]), "+f"(acc[J][1]),                \
                                   "+f"(acc[J][2]), "+f"(acc[J][3])                 \
                                 : "r"(a0), "r"(a1), "r"(a2), "r"(a3),              \
                                   "r"(B0), "r"(B1))
                MMA(0, q0, q2);
                MMA(1, q1, q3);
                MMA(2, p0, p2);
                MMA(3, p1, p3);
                #undef MMA
            }

            if (kt + 1 < 32) {  // stash prefetched tile into the other buffer
                int off0 = lrow * 128 + lch0 * 16;
                *(uint4*)(sm[buf ^ 1] + (off0 ^ ((lrow & 7) << 4))) = pv0;
                *(uint4*)(sm[buf ^ 1] + ((off0 + 16) ^ ((lrow & 7) << 4))) = pv1;
            }
            __syncthreads();
        }

        // epilogue: write channel 2 + minmax
        float* o2 = out + ((size_t)(b * 3 + 2)) * 4096;
        const int r0 = wm * 16 + (lane >> 2);
        const int c0 = wn * 32 + (lane & 3) * 2;
        float mn = 3.0e38f, mx = -3.0e38f;
        #pragma unroll
        for (int j = 0; j < 4; ++j) {
            int cc = c0 + j * 8;
            float2 lo = make_float2(acc[j][0], acc[j][1]);
            float2 hi = make_float2(acc[j][2], acc[j][3]);
            *(float2*)(o2 + r0 * 64 + cc) = lo;
            *(float2*)(o2 + (r0 + 8) * 64 + cc) = hi;
            mn = fminf(mn, fminf(fminf(lo.x, lo.y), fminf(hi.x, hi.y)));
            mx = fmaxf(mx, fmaxf(fmaxf(lo.x, lo.y), fmaxf(hi.x, hi.y)));
        }
        block_minmax_atomic(mn, mx, 2);
    } else {
        // ================= views branch =================
        const int b = blockIdx.x - 64;

        float* srow = (float*)smraw;                    // 512 f  @0
        float* scol = (float*)(smraw + 2048);           // 2048 f @2048
        int*   i0t  = (int*)(smraw + 10240);            // [2][64]
        int*   i1t  = (int*)(smraw + 10752);            // [2][64]
        float* wt   = (float*)(smraw + 11264);          // [2][64]

        srow[t]       = g_rowmean[b * EE + t];
        srow[t + 256] = g_rowmean[b * EE + t + 256];

        {   // column means: reduce 16 partials
            float4 s0 = make_float4(0.f, 0.f, 0.f, 0.f);
            float4 s1 = make_float4(0.f, 0.f, 0.f, 0.f);
            const float4* cp = (const float4*)g_colpart + (size_t)b * 16 * (NN / 4);
            #pragma unroll
            for (int c = 0; c < 16; ++c) {
                float4 v0 = cp[c * (NN / 4) + t];
                float4 v1 = cp[c * (NN / 4) + t + 256];
                s0.x += v0.x; s0.y += v0.y; s0.z += v0.z; s0.w += v0.w;
                s1.x += v1.x; s1.y += v1.y; s1.z += v1.z; s1.w += v1.w;
            }
            const float k = 1.0f / EE;
            s0.x *= k; s0.y *= k; s0.z *= k; s0.w *= k;
            s1.x *= k; s1.y *= k; s1.z *= k; s1.w *= k;
            ((float4*)scol)[t] = s0;
            ((float4*)scol)[t + 256] = s1;
        }

        if (t < 128) {  // tap tables (fp32-exact: denominators are powers of 2)
            int sel = t >> 6, o = t & 63;
            int gs = sel ? 46 : 23;
            float src = ((float)o + 0.5f) * ((float)gs / (float)IMGS) - 0.5f;
            src = fminf(fmaxf(src, 0.f), (float)(gs - 1));
            int p0 = (int)floorf(src);
            i0t[sel * 64 + o] = p0;
            i1t[sel * 64 + o] = min(p0 + 1, gs - 1);
            wt[sel * 64 + o]  = src - (float)p0;
        }
        __syncthreads();

        #pragma unroll
        for (int sel = 0; sel < 2; ++sel) {
            const float* v = sel ? scol : srow;
            const int L = sel ? NN : EE;
            const int gs = sel ? 46 : 23;
            float mn = 3.0e38f, mx = -3.0e38f;
            #pragma unroll
            for (int u = 0; u < 16; ++u) {
                int ij = t + 256 * u;
                int i = ij >> 6, j = ij & 63;
                int i0 = i0t[sel * 64 + i], i1 = i1t[sel * 64 + i];
                int j0 = i0t[sel * 64 + j], j1 = i1t[sel * 64 + j];
                float wi = wt[sel * 64 + i], wj = wt[sel * 64 + j];
                int p00 = i0 * gs + j0, p01 = i0 * gs + j1;
                int p10 = i1 * gs + j0, p11 = i1 * gs + j1;
                float v00 = (p00 < L) ? v[p00] : 0.f;
                float v01 = (p01 < L) ? v[p01] : 0.f;
                float v10 = (p10 < L) ? v[p10] : 0.f;
                float v11 = (p11 < L) ? v[p11] : 0.f;
                float val = (1.f - wi) * ((1.f - wj) * v00 + wj * v01) +
                            wi * ((1.f - wj) * v10 + wj * v11);
                out[((size_t)(b * 3 + sel)) * 4096 + ij] = val;
                mn = fminf(mn, val); mx = fmaxf(mx, val);
            }
            block_minmax_atomic(mn, mx, sel);
        }
    }
}

// global per-channel min-max normalization, in place (float4 grid-stride)
__global__ void __launch_bounds__(256) k_norm(float* __restrict__ out) {
    float4* o4 = (float4*)out;
    const int n4 = BB * 3 * 4096 / 4;              // 196608
    float lo[3], inv[3];
    #pragma unroll
    for (int c = 0; c < 3; ++c) {
        float l = fdec(g_mm[2 * c]);
        float h = fdec(g_mm[2 * c + 1]);
        float d = h - l;
        lo[c] = l;
        inv[c] = (d < EPSF) ? 0.f : 1.0f / (d + EPSF);
    }
    for (int i = blockIdx.x * blockDim.x + threadIdx.x; i < n4;
         i += gridDim.x * blockDim.x) {
        int ch = (i >> 10) % 3;                    // 1024 float4 per channel image
        float4 v = o4[i];
        v.x = (v.x - lo[ch]) * inv[ch];
        v.y = (v.y - lo[ch]) * inv[ch];
        v.z = (v.z - lo[ch]) * inv[ch];
        v.w = (v.w - lo[ch]) * inv[ch];
        o4[i] = v;
    }
}

extern "C" void kernel_launch(void* const* d_in, const int* in_sizes, int n_in,
                              void* d_out, int out_size) {
    const float* x = (const float*)d_in[0];
    float* out = (float*)d_out;

    k_pass1<<<dim3(16, 64), 256>>>(x);
    k_fused<<<128, 256>>>(out);
    k_norm<<<192, 256>>>(out);
}

// round 10
// speedup vs baseline: 1.1324x; 1.1324x over previous
#include <cuda_runtime.h>
#include <cuda_bf16.h>
#include <math.h>

#define BB   64
#define EE   512
#define NN   2048
#define IMGS 64
#define EPSF 1e-8f

// ---- scratch (static device globals; no allocation) ----
__device__ __nv_bfloat16 g_y[BB * IMGS * NN];   // 16 MiB  [b][o][n]
__device__ float g_colpart[BB * 32 * NN];       // 16 MiB  [b][chunk][n]
__device__ float g_rowmean[BB * EE];            // 128 KiB
__device__ unsigned g_mm[6];                    // min/max per channel (encoded)

// order-preserving float<->uint encoding for atomic min/max
__device__ __forceinline__ unsigned fenc(float f) {
    unsigned u = __float_as_uint(f);
    return (u & 0x80000000u) ? ~u : (u | 0x80000000u);
}
__device__ __forceinline__ float fdec(unsigned e) {
    unsigned u = (e & 0x80000000u) ? (e ^ 0x80000000u) : ~e;
    return __uint_as_float(u);
}

__device__ __forceinline__ unsigned smem_u32(const void* p) {
    unsigned a;
    asm("{ .reg .u64 t; cvta.to.shared.u64 t, %1; cvt.u32.u64 %0, t; }"
        : "=r"(a) : "l"(p));
    return a;
}

// block-wide minmax -> global atomics (entry sync so it can be called twice)
__device__ __forceinline__ void block_minmax_atomic(float mn, float mx, int ch) {
    __shared__ float smn[8], smx[8];
    __syncthreads();
    #pragma unroll
    for (int o = 16; o; o >>= 1) {
        mn = fminf(mn, __shfl_down_sync(0xFFFFFFFFu, mn, o));
        mx = fmaxf(mx, __shfl_down_sync(0xFFFFFFFFu, mx, o));
    }
    int lane = threadIdx.x & 31, warp = threadIdx.x >> 5;
    if (lane == 0) { smn[warp] = mn; smx[warp] = mx; }
    __syncthreads();
    if (threadIdx.x == 0) {
        float a = smn[0], c = smx[0];
        #pragma unroll
        for (int w = 1; w < 8; ++w) { a = fminf(a, smn[w]); c = fmaxf(c, smx[w]); }
        atomicMin(&g_mm[2 * ch], fenc(a));
        atomicMax(&g_mm[2 * ch + 1], fenc(c));
    }
}

// ---------------------------------------------------------------------------
// Pass 1: one CTA per (batch, 16-row chunk). Streams input once.
// In-loop shuffle reductions (no live per-row accumulator array -> low regs).
//  - per-row mean -> g_rowmean
//  - rows chunk*16+{3,4} -> y row 2c ; +{11,12} -> y row 2c+1 (smem stash)
//  - partial column sums over the 16 rows -> g_colpart
// ---------------------------------------------------------------------------
__global__ void __launch_bounds__(256) k_pass1(const float* __restrict__ x) {
    const int chunk = blockIdx.x;   // 0..31
    const int b     = blockIdx.y;   // 0..63
    const int t     = threadIdx.x;  // 0..255
    const int lane  = t & 31, warp = t >> 5;

    if (chunk == 0 && b == 0) {     // fold g_mm init in (consumers run later)
        if (t < 3) g_mm[2 * t] = 0xFFFFFFFFu;
        else if (t < 6) g_mm[2 * (t - 3) + 1] = 0u;
    }

    __shared__ float4 rows[4][512];          // rows 3,4,11,12 (32 KB)
    __shared__ float wsum[8][16], wsq[8][4];
    __shared__ float rsum[16], rsq[4];

    float4 cs0 = make_float4(0.f, 0.f, 0.f, 0.f);
    float4 cs1 = make_float4(0.f, 0.f, 0.f, 0.f);

    const float4* base = (const float4*)x + (size_t)(b * EE + chunk * 16) * (NN / 4);

    #pragma unroll
    for (int r = 0; r < 16; ++r) {
        const float4* rp = base + (size_t)r * (NN / 4);
        float4 v0 = rp[t];
        float4 v1 = rp[t + 256];

        cs0.x += v0.x; cs0.y += v0.y; cs0.z += v0.z; cs0.w += v0.w;
        cs1.x += v1.x; cs1.y += v1.y; cs1.z += v1.z; cs1.w += v1.w;

        float s = (v0.x + v0.y) + (v0.z + v0.w) + (v1.x + v1.y) + (v1.z + v1.w);
        #pragma unroll
        for (int o = 16; o; o >>= 1)
            s += __shfl_down_sync(0xFFFFFFFFu, s, o);
        if (lane == 0) wsum[warp][r] = s;

        if (r == 3 || r == 4 || r == 11 || r == 12) {   // selected rows
            const int si = (r >= 8) ? (r - 9) : (r - 3); // 3,4,11,12 -> 0,1,2,3
            rows[si][t] = v0; rows[si][t + 256] = v1;
            float q = v0.x * v0.x + v0.y * v0.y + v0.z * v0.z + v0.w * v0.w +
                      v1.x * v1.x + v1.y * v1.y + v1.z * v1.z + v1.w * v1.w;
            #pragma unroll
            for (int o = 16; o; o >>= 1)
                q += __shfl_down_sync(0xFFFFFFFFu, q, o);
            if (lane == 0) wsq[warp][si] = q;
        }
    }
    __syncthreads();
    if (t < 16) {
        float S = 0.f;
        #pragma unroll
        for (int w = 0; w < 8; ++w) S += wsum[w][t];
        rsum[t] = S;
        g_rowmean[b * EE + chunk * 16 + t] = S * (1.0f / NN);
    } else if (t < 20) {
        const int p = t - 16;
        float Q = 0.f;
        #pragma unroll
        for (int w = 0; w < 8; ++w) Q += wsq[w][p];
        rsq[p] = Q;
    }
    __syncthreads();

    #pragma unroll
    for (int half = 0; half < 2; ++half) {  // half 0 -> y row 2c, 1 -> 2c+1
        const int sA = half * 2, sB = half * 2 + 1;
        const int rA = half ? 11 : 3, rB = half ? 12 : 4;
        const float mA = rsum[rA] * (1.0f / NN);
        const float mB = rsum[rB] * (1.0f / NN);
        const float iA = 0.5f / (sqrtf(fmaxf(rsq[sA] - (float)NN * mA * mA, 0.f)) + EPSF);
        const float iB = 0.5f / (sqrtf(fmaxf(rsq[sB] - (float)NN * mB * mB, 0.f)) + EPSF);
        uint2* yb = (uint2*)(g_y + (size_t)(b * IMGS + chunk * 2 + half) * NN);
        #pragma unroll
        for (int u = 0; u < 2; ++u) {
            float4 a = rows[sA][t + 256 * u];
            float4 c = rows[sB][t + 256 * u];
            float4 y;
            y.x = (a.x - mA) * iA + (c.x - mB) * iB;
            y.y = (a.y - mA) * iA + (c.y - mB) * iB;
            y.z = (a.z - mA) * iA + (c.z - mB) * iB;
            y.w = (a.w - mA) * iA + (c.w - mB) * iB;
            __nv_bfloat162 h0 = __floats2bfloat162_rn(y.x, y.y);
            __nv_bfloat162 h1 = __floats2bfloat162_rn(y.z, y.w);
            uint2 pk;
            pk.x = *(unsigned*)&h0;
            pk.y = *(unsigned*)&h1;
            yb[t + 256 * u] = pk;
        }
    }

    float4* cp = (float4*)g_colpart + (size_t)(b * 32 + chunk) * (NN / 4);
    cp[t] = cs0; cp[t + 256] = cs1;
}

// ---------------------------------------------------------------------------
// Fused middle kernel, grid = 128:
//  blocks 0..63  : corr GEMM (1 CTA per batch), bf16 mma.sync, K-tile=128,
//                  single-stage register prefetch (16 outer iterations)
//  blocks 64..127: temporal+spatial bilinear views (1 CTA per batch)
// ---------------------------------------------------------------------------
__global__ void __launch_bounds__(256) k_fused(float* __restrict__ out) {
    __shared__ __align__(16) char smraw[32768];  // union: gemm dbuf / view arrays
    const int t = threadIdx.x;

    if (blockIdx.x < 64) {
        // ================= GEMM branch =================
        const int b    = blockIdx.x;
        const int warp = t >> 5, lane = t & 31;
        const int wm   = warp >> 1;        // 0..3 -> rows 16*wm
        const int wn   = warp & 1;         // 0..1 -> cols 32*wn

        char (*sm)[64 * 256] = (char (*)[64 * 256])smraw;  // [2][16384] dbuf
        const __nv_bfloat16* Yb = g_y + (size_t)b * IMGS * NN;

        const int lrow = t >> 2;           // loader row 0..63
        const int lc   = t & 3;            // chunk group: cb = lc*16 + u*64

        const int arow  = wm * 16 + (lane & 15);
        const int brow0 = wn * 32 + (lane & 15);
        const int brow1 = wn * 32 + 16 + (lane & 15);
        const int chalf = (lane >> 4) * 16;
        const unsigned smb = smem_u32(smraw);

        float acc[4][4];
        #pragma unroll
        for (int j = 0; j < 4; ++j)
            #pragma unroll
            for (int r = 0; r < 4; ++r) acc[j][r] = 0.f;

        uint4 pv[4];
        {   // preload K-tile 0 (row lrow, 4 x 16B at cb = lc*16 + u*64)
            const uint4* src = (const uint4*)(Yb + (size_t)lrow * NN);
            #pragma unroll
            for (int u = 0; u < 4; ++u) pv[u] = src[lc + u * 4];
            #pragma unroll
            for (int u = 0; u < 4; ++u) {
                int off = lrow * 256 + lc * 16 + u * 64;
                *(uint4*)(smraw + (off ^ ((lrow & 7) << 4))) = pv[u];
            }
        }
        __syncthreads();

        for (int kt = 0; kt < 16; ++kt) {
            const int buf = kt & 1;
            if (kt + 1 < 16) {  // issue next-tile loads early (regs, MLP=4)
                const uint4* src = (const uint4*)(Yb + (size_t)lrow * NN + (kt + 1) * 128);
                #pragma unroll
                for (int u = 0; u < 4; ++u) pv[u] = src[lc + u * 4];
            }

            const unsigned base = smb + buf * (64 * 256);
            #pragma unroll
            for (int ks = 0; ks < 8; ++ks) {
                const int kb = ks * 32;  // 16 bf16 per k-step
                unsigned a0, a1, a2, a3;
                {
                    int off = arow * 256 + kb + chalf;
                    unsigned ad = base + (off ^ ((arow & 7) << 4));
                    asm volatile("ldmatrix.sync.aligned.m8n8.x4.shared.b16 "
                                 "{%0,%1,%2,%3}, [%4];"
                                 : "=r"(a0), "=r"(a1), "=r"(a2), "=r"(a3) : "r"(ad));
                }
                unsigned q0, q1, q2, q3, p0, p1, p2, p3;
                {
                    int off = brow0 * 256 + kb + chalf;
                    unsigned ad = base + (off ^ ((brow0 & 7) << 4));
                    asm volatile("ldmatrix.sync.aligned.m8n8.x4.shared.b16 "
                                 "{%0,%1,%2,%3}, [%4];"
                                 : "=r"(q0), "=r"(q1), "=r"(q2), "=r"(q3) : "r"(ad));
                }
                {
                    int off = brow1 * 256 + kb + chalf;
                    unsigned ad = base + (off ^ ((brow1 & 7) << 4));
                    asm volatile("ldmatrix.sync.aligned.m8n8.x4.shared.b16 "
                                 "{%0,%1,%2,%3}, [%4];"
                                 : "=r"(p0), "=r"(p1), "=r"(p2), "=r"(p3) : "r"(ad));
                }
                #define MMA(J, B0, B1)                                              \
                    asm volatile("mma.sync.aligned.m16n8k16.row.col.f32.bf16.bf16.f32 " \
                                 "{%0,%1,%2,%3}, {%4,%5,%6,%7}, {%8,%9}, {%0,%1,%2,%3};" \
                                 : "+f"(acc[J][0]), "+f"(acc[J][1]),                \
                                   "+f"(acc[J][2]), "+f"(acc[J][3])                 \
                                 : "r"(a0), "r"(a1), "r"(a2), "r"(a3),              \
                                   "r"(B0), "r"(B1))
                MMA(0, q0, q2);
                MMA(1, q1, q3);
                MMA(2, p0, p2);
                MMA(3, p1, p3);
                #undef MMA
            }

            if (kt + 1 < 16) {  // stash prefetched tile into the other buffer
                #pragma unroll
                for (int u = 0; u < 4; ++u) {
                    int off = lrow * 256 + lc * 16 + u * 64;
                    *(uint4*)(sm[buf ^ 1] + (off ^ ((lrow & 7) << 4))) = pv[u];
                }
            }
            __syncthreads();
        }

        // epilogue: write channel 2 + minmax
        float* o2 = out + ((size_t)(b * 3 + 2)) * 4096;
        const int r0 = wm * 16 + (lane >> 2);
        const int c0 = wn * 32 + (lane & 3) * 2;
        float mn = 3.0e38f, mx = -3.0e38f;
        #pragma unroll
        for (int j = 0; j < 4; ++j) {
            int cc = c0 + j * 8;
            float2 lo = make_float2(acc[j][0], acc[j][1]);
            float2 hi = make_float2(acc[j][2], acc[j][3]);
            *(float2*)(o2 + r0 * 64 + cc) = lo;
            *(float2*)(o2 + (r0 + 8) * 64 + cc) = hi;
            mn = fminf(mn, fminf(fminf(lo.x, lo.y), fminf(hi.x, hi.y)));
            mx = fmaxf(mx, fmaxf(fmaxf(lo.x, lo.y), fmaxf(hi.x, hi.y)));
        }
        block_minmax_atomic(mn, mx, 2);
    } else {
        // ================= views branch =================
        const int b = blockIdx.x - 64;

        float* srow = (float*)smraw;                    // 512 f  @0
        float* scol = (float*)(smraw + 2048);           // 2048 f @2048
        int*   i0t  = (int*)(smraw + 10240);            // [2][64]
        int*   i1t  = (int*)(smraw + 10752);            // [2][64]
        float* wt   = (float*)(smraw + 11264);          // [2][64]

        srow[t]       = g_rowmean[b * EE + t];
        srow[t + 256] = g_rowmean[b * EE + t + 256];

        {   // column means: reduce 32 partials
            float4 s0 = make_float4(0.f, 0.f, 0.f, 0.f);
            float4 s1 = make_float4(0.f, 0.f, 0.f, 0.f);
            const float4* cp = (const float4*)g_colpart + (size_t)b * 32 * (NN / 4);
            #pragma unroll 8
            for (int c = 0; c < 32; ++c) {
                float4 v0 = cp[c * (NN / 4) + t];
                float4 v1 = cp[c * (NN / 4) + t + 256];
                s0.x += v0.x; s0.y += v0.y; s0.z += v0.z; s0.w += v0.w;
                s1.x += v1.x; s1.y += v1.y; s1.z += v1.z; s1.w += v1.w;
            }
            const float k = 1.0f / EE;
            s0.x *= k; s0.y *= k; s0.z *= k; s0.w *= k;
            s1.x *= k; s1.y *= k; s1.z *= k; s1.w *= k;
            ((float4*)scol)[t] = s0;
            ((float4*)scol)[t + 256] = s1;
        }

        if (t < 128) {  // tap tables (fp32-exact: denominators are powers of 2)
            int sel = t >> 6, o = t & 63;
            int gs = sel ? 46 : 23;
            float src = ((float)o + 0.5f) * ((float)gs / (float)IMGS) - 0.5f;
            src = fminf(fmaxf(src, 0.f), (float)(gs - 1));
            int p0 = (int)floorf(src);
            i0t[sel * 64 + o] = p0;
            i1t[sel * 64 + o] = min(p0 + 1, gs - 1);
            wt[sel * 64 + o]  = src - (float)p0;
        }
        __syncthreads();

        #pragma unroll
        for (int sel = 0; sel < 2; ++sel) {
            const float* v = sel ? scol : srow;
            const int L = sel ? NN : EE;
            const int gs = sel ? 46 : 23;
            float mn = 3.0e38f, mx = -3.0e38f;
            #pragma unroll
            for (int u = 0; u < 16; ++u) {
                int ij = t + 256 * u;
                int i = ij >> 6, j = ij & 63;
                int i0 = i0t[sel * 64 + i], i1 = i1t[sel * 64 + i];
                int j0 = i0t[sel * 64 + j], j1 = i1t[sel * 64 + j];
                float wi = wt[sel * 64 + i], wj = wt[sel * 64 + j];
                int p00 = i0 * gs + j0, p01 = i0 * gs + j1;
                int p10 = i1 * gs + j0, p11 = i1 * gs + j1;
                float v00 = (p00 < L) ? v[p00] : 0.f;
                float v01 = (p01 < L) ? v[p01] : 0.f;
                float v10 = (p10 < L) ? v[p10] : 0.f;
                float v11 = (p11 < L) ? v[p11] : 0.f;
                float val = (1.f - wi) * ((1.f - wj) * v00 + wj * v01) +
                            wi * ((1.f - wj) * v10 + wj * v11);
                out[((size_t)(b * 3 + sel)) * 4096 + ij] = val;
                mn = fminf(mn, val); mx = fmaxf(mx, val);
            }
            block_minmax_atomic(mn, mx, sel);
        }
    }
}

// global per-channel min-max normalization, in place (float4 grid-stride)
__global__ void __launch_bounds__(256) k_norm(float* __restrict__ out) {
    float4* o4 = (float4*)out;
    const int n4 = BB * 3 * 4096 / 4;              // 196608
    float lo[3], inv[3];
    #pragma unroll
    for (int c = 0; c < 3; ++c) {
        float l = fdec(g_mm[2 * c]);
        float h = fdec(g_mm[2 * c + 1]);
        float d = h - l;
        lo[c] = l;
        inv[c] = (d < EPSF) ? 0.f : 1.0f / (d + EPSF);
    }
    for (int i = blockIdx.x * blockDim.x + threadIdx.x; i < n4;
         i += gridDim.x * blockDim.x) {
        int ch = (i >> 10) % 3;                    // 1024 float4 per channel image
        float4 v = o4[i];
        v.x = (v.x - lo[ch]) * inv[ch];
        v.y = (v.y - lo[ch]) * inv[ch];
        v.z = (v.z - lo[ch]) * inv[ch];
        v.w = (v.w - lo[ch]) * inv[ch];
        o4[i] = v;
    }
}

extern "C" void kernel_launch(void* const* d_in, const int* in_sizes, int n_in,
                              void* d_out, int out_size) {
    const float* x = (const float*)d_in[0];
    float* out = (float*)d_out;

    k_pass1<<<dim3(32, 64), 256>>>(x);
    k_fused<<<128, 256>>>(out);
    k_norm<<<192, 256>>>(out);
}